// round 6
// baseline (speedup 1.0000x reference)
#include <cuda_runtime.h>
#include <cuda_fp16.h>
#include <cstdint>

// ---------------------------------------------------------------------------
// SimpleGCN on B200: CSR aggregation + fp16-compressed h.
//   h = act(in) @ W stored as __half (128B/row) -> gather reads halve.
//   Accumulation, norms, acc buffers, output all stay fp32.
// (Resubmission: round-5 bench failed on container acquisition, not code.)
// ---------------------------------------------------------------------------

#define MAXN (1 << 17)
#define MAXE (1 << 21)
#define FDIM 64

struct alignas(16) H8 { __half2 a, b, c, d; };   // 8 halves = 16 B

__device__ __half g_h[(size_t)MAXN * FDIM];      // fp16 transformed features
__device__ float  g_acc[(size_t)MAXN * FDIM];    // fp32 layer outputs
__device__ float  g_dinv[MAXN];
__device__ int    g_cnt[MAXN];
__device__ int    g_row[MAXN];
__device__ int    g_cur[MAXN];
__device__ int    g_bsum[256];
__device__ int2   g_edata[MAXE];                 // {src, bitcast(norm)}
__device__ int    g_is64;

// --- dtype detection: int64 LE with small values has zero odd 32-bit words
__global__ void k_detect(const unsigned int* __restrict__ w, long long nwords) {
    __shared__ int cnt;
    if (threadIdx.x == 0) cnt = 0;
    __syncthreads();
    int zeros = 0;
    for (long long i = threadIdx.x; i < 2048 && i < nwords; i += blockDim.x)
        if ((i & 1) && w[i] == 0u) zeros++;
    atomicAdd(&cnt, zeros);
    __syncthreads();
    if (threadIdx.x == 0) g_is64 = (cnt > 512) ? 1 : 0;
}

__device__ __forceinline__ int load_idx(const void* e, long long pos) {
    if (g_is64) return (int)((const long long*)e)[pos];
    return ((const int*)e)[pos];
}

__global__ void k_zero2(int n) {
    int i = blockIdx.x * blockDim.x + threadIdx.x;
    if (i < n) { g_cnt[i] = 0; g_cur[i] = 0; }
}

__global__ void k_deg(const void* __restrict__ e, long long E) {
    long long i = (long long)blockIdx.x * blockDim.x + threadIdx.x;
    if (i >= E) return;
    atomicAdd(&g_cnt[load_idx(e, E + i)], 1);
}

__global__ void k_dinv(int n) {
    int i = blockIdx.x * blockDim.x + threadIdx.x;
    if (i < n) g_dinv[i] = rsqrtf((float)(1 + g_cnt[i]));
}

// --- exclusive scan of g_cnt -> g_row
__global__ void k_scan1(int n) {
    __shared__ int sh[1024];
    int i = blockIdx.x * 1024 + threadIdx.x;
    int v = (i < n) ? g_cnt[i] : 0;
    sh[threadIdx.x] = v;
    __syncthreads();
#pragma unroll
    for (int off = 1; off < 1024; off <<= 1) {
        int t = (threadIdx.x >= off) ? sh[threadIdx.x - off] : 0;
        __syncthreads();
        sh[threadIdx.x] += t;
        __syncthreads();
    }
    if (i < n) g_row[i] = sh[threadIdx.x] - v;
    if (threadIdx.x == 1023) g_bsum[blockIdx.x] = sh[1023];
}

__global__ void k_scan2(int nb) {
    __shared__ int sh[256];
    int v = (threadIdx.x < nb) ? g_bsum[threadIdx.x] : 0;
    sh[threadIdx.x] = v;
    __syncthreads();
#pragma unroll
    for (int off = 1; off < 256; off <<= 1) {
        int t = (threadIdx.x >= off) ? sh[threadIdx.x - off] : 0;
        __syncthreads();
        sh[threadIdx.x] += t;
        __syncthreads();
    }
    if (threadIdx.x < nb) g_bsum[threadIdx.x] = sh[threadIdx.x] - v;
}

__global__ void k_scan3(int n) {
    int i = blockIdx.x * 1024 + threadIdx.x;
    if (i < n) g_row[i] += g_bsum[blockIdx.x];
}

__global__ void k_fill(const void* __restrict__ e, long long E) {
    long long i = (long long)blockIdx.x * blockDim.x + threadIdx.x;
    if (i >= E) return;
    int s, d;
    if (g_is64) {
        const long long* p = (const long long*)e;
        s = (int)p[i]; d = (int)p[E + i];
    } else {
        const int* p = (const int*)e;
        s = p[i]; d = p[E + i];
    }
    int pos = g_row[d] + atomicAdd(&g_cur[d], 1);
    g_edata[pos] = make_int2(s, __float_as_int(g_dinv[s] * g_dinv[d]));
}

// --- GEMM: h = act(in) @ W, epilogue converts to fp16 (H8 = STG.128)
template <int LRELU>
__global__ void __launch_bounds__(128)
k_gemm(const float* __restrict__ in, const float* __restrict__ W,
       __half* __restrict__ h, int n) {
    __shared__ float Ws[FDIM * FDIM];
    for (int i = threadIdx.x; i < FDIM * FDIM; i += blockDim.x) Ws[i] = W[i];
    __syncthreads();

    int r = blockIdx.x * blockDim.x + threadIdx.x;
    if (r >= n) return;

    float a[FDIM];
#pragma unroll
    for (int j = 0; j < FDIM; j++) a[j] = 0.0f;

    const float4* x4 = (const float4*)(in + (size_t)r * FDIM);
#pragma unroll 4
    for (int k4 = 0; k4 < FDIM / 4; k4++) {
        float4 xv = __ldg(x4 + k4);
        float xs[4] = {xv.x, xv.y, xv.z, xv.w};
#pragma unroll
        for (int kk = 0; kk < 4; kk++) {
            float xk = xs[kk];
            if (LRELU) xk = xk > 0.0f ? xk : 0.01f * xk;
            const float4* Wr = (const float4*)&Ws[(k4 * 4 + kk) * FDIM];
#pragma unroll
            for (int j = 0; j < FDIM / 4; j++) {
                float4 w = Wr[j];
                a[4 * j + 0] = fmaf(xk, w.x, a[4 * j + 0]);
                a[4 * j + 1] = fmaf(xk, w.y, a[4 * j + 1]);
                a[4 * j + 2] = fmaf(xk, w.z, a[4 * j + 2]);
                a[4 * j + 3] = fmaf(xk, w.w, a[4 * j + 3]);
            }
        }
    }

    H8* hr = (H8*)(h + (size_t)r * FDIM);
#pragma unroll
    for (int j = 0; j < 8; j++) {
        H8 v;
        v.a = __floats2half2_rn(a[8 * j + 0], a[8 * j + 1]);
        v.b = __floats2half2_rn(a[8 * j + 2], a[8 * j + 3]);
        v.c = __floats2half2_rn(a[8 * j + 4], a[8 * j + 5]);
        v.d = __floats2half2_rn(a[8 * j + 6], a[8 * j + 7]);
        hr[j] = v;
    }
}

// --- CSR gather: 8 threads per node, each owns 8 columns (16B fp16 slab).
//     out[i] = sum_e h[src_e]*norm_e + h[i]*dinv[i]^2 + b  (fp32 accum)
__device__ __forceinline__ void acc_h8(const H8& v, float nn, float* a) {
    float2 f0 = __half22float2(v.a);
    float2 f1 = __half22float2(v.b);
    float2 f2 = __half22float2(v.c);
    float2 f3 = __half22float2(v.d);
    a[0] = fmaf(f0.x, nn, a[0]); a[1] = fmaf(f0.y, nn, a[1]);
    a[2] = fmaf(f1.x, nn, a[2]); a[3] = fmaf(f1.y, nn, a[3]);
    a[4] = fmaf(f2.x, nn, a[4]); a[5] = fmaf(f2.y, nn, a[5]);
    a[6] = fmaf(f3.x, nn, a[6]); a[7] = fmaf(f3.y, nn, a[7]);
}

__global__ void __launch_bounds__(256)
k_gather(const __half* __restrict__ h, float* __restrict__ out,
         const float* __restrict__ b, int n) {
    int node = blockIdx.x * 32 + (threadIdx.x >> 3);
    if (node >= n) return;
    int c8 = threadIdx.x & 7;                 // owns cols [8*c8, 8*c8+8)

    const H8* h8 = (const H8*)h;              // 8 H8 per row
    int start = g_row[node];
    int deg   = g_cnt[node];
    float di  = g_dinv[node];
    float sn  = di * di;

    float a[8];
    {
        H8 self = h8[(size_t)node * 8 + c8];
        float2 f0 = __half22float2(self.a), f1 = __half22float2(self.b);
        float2 f2 = __half22float2(self.c), f3 = __half22float2(self.d);
        const float4* bv4 = (const float4*)(b + c8 * 8);
        float4 b0 = __ldg(bv4), b1 = __ldg(bv4 + 1);
        a[0] = fmaf(f0.x, sn, b0.x); a[1] = fmaf(f0.y, sn, b0.y);
        a[2] = fmaf(f1.x, sn, b0.z); a[3] = fmaf(f1.y, sn, b0.w);
        a[4] = fmaf(f2.x, sn, b1.x); a[5] = fmaf(f2.y, sn, b1.y);
        a[6] = fmaf(f3.x, sn, b1.z); a[7] = fmaf(f3.y, sn, b1.w);
    }

    const int2* ed = g_edata + start;
    int e = 0;
    for (; e + 4 <= deg; e += 4) {
        int2 e0 = ed[e], e1 = ed[e + 1], e2 = ed[e + 2], e3 = ed[e + 3];
        H8 v0 = h8[(size_t)e0.x * 8 + c8];
        H8 v1 = h8[(size_t)e1.x * 8 + c8];
        H8 v2 = h8[(size_t)e2.x * 8 + c8];
        H8 v3 = h8[(size_t)e3.x * 8 + c8];
        acc_h8(v0, __int_as_float(e0.y), a);
        acc_h8(v1, __int_as_float(e1.y), a);
        acc_h8(v2, __int_as_float(e2.y), a);
        acc_h8(v3, __int_as_float(e3.y), a);
    }
    for (; e < deg; e++) {
        int2 ee = ed[e];
        H8 v = h8[(size_t)ee.x * 8 + c8];
        acc_h8(v, __int_as_float(ee.y), a);
    }

    float4* o4 = (float4*)(out + (size_t)node * FDIM + c8 * 8);
    o4[0] = make_float4(a[0], a[1], a[2], a[3]);
    o4[1] = make_float4(a[4], a[5], a[6], a[7]);
}

extern "C" void kernel_launch(void* const* d_in, const int* in_sizes, int n_in,
                              void* d_out, int out_size) {
    const float* x  = (const float*)d_in[0];
    const void*  ei = d_in[1];
    const float* W1 = (const float*)d_in[2];
    const float* b1 = (const float*)d_in[3];
    const float* W2 = (const float*)d_in[4];
    const float* b2 = (const float*)d_in[5];
    const float* W3 = (const float*)d_in[6];
    const float* b3 = (const float*)d_in[7];
    float* out = (float*)d_out;

    int n = in_sizes[0] / FDIM;
    long long E = (long long)in_sizes[1] / 2;

    __half* hbuf;
    float* accbuf;
    cudaGetSymbolAddress((void**)&hbuf, g_h);
    cudaGetSymbolAddress((void**)&accbuf, g_acc);

    int nb_n    = (n + 255) / 256;
    int nb_e    = (int)((E + 255) / 256);
    int nb_g    = (n + 127) / 128;
    int nb_scan = (n + 1023) / 1024;
    int nb_ga   = (n + 31) / 32;

    // --- prep: CSR build
    k_detect<<<1, 256>>>((const unsigned int*)ei, 2 * E);
    k_zero2<<<nb_n, 256>>>(n);
    k_deg<<<nb_e, 256>>>(ei, E);
    k_dinv<<<nb_n, 256>>>(n);
    k_scan1<<<nb_scan, 1024>>>(n);
    k_scan2<<<1, 256>>>(nb_scan);
    k_scan3<<<nb_scan, 1024>>>(n);
    k_fill<<<nb_e, 256>>>(ei, E);

    // --- layer 1
    k_gemm<0><<<nb_g, 128>>>(x, W1, hbuf, n);
    k_gather<<<nb_ga, 256>>>(hbuf, accbuf, b1, n);
    // --- layer 2
    k_gemm<1><<<nb_g, 128>>>(accbuf, W2, hbuf, n);
    k_gather<<<nb_ga, 256>>>(hbuf, accbuf, b2, n);
    // --- layer 3
    k_gemm<1><<<nb_g, 128>>>(accbuf, W3, hbuf, n);
    k_gather<<<nb_ga, 256>>>(hbuf, out, b3, n);
}